// round 10
// baseline (speedup 1.0000x reference)
#include <cuda_runtime.h>
#include <float.h>

// ---------------------------------------------------------------------------
// PointSIFT select_cube + group, fused 2-kernel pipeline.
//   k_build: per-batch block; smem histogram + warp-shuffle scan + scatter
//            (counting sort on 10^3 grid, cell size == radius).
//   k_query_gather: 8 warps/block, ONE warp per query, no block barriers.
//     Search: the 4..9 z-spans (3x3 xy-cells, z contiguous) are virtually
//       concatenated; a shuffle prefix-scan + per-warp smem (excl,dlt) table
//       maps global candidate index -> sorted-array index, so ~110 candidates
//       run as ~4 dense 32-lane iterations with independent LDG.128s.
//       Winners via per-warp smem atomicMin on 64-bit (dist_bits<<32 | j).
//     Gather: warp q owns query q; features via float4 loads staged in smem,
//       write-out as aligned float4 stores.
//
// Output layout (float32, reference return order):
//   [0 .. BN*8*3)             grouped_xyz   [B,N,8,3]
//   [.. +BN*8*(3+C))          grouped_points[B,N,8,3+C]
//   [.. +BN*8)                idx (int32 cast to float) [B,N,8]
// ---------------------------------------------------------------------------

#define GRIDR   10
#define NCELL   (GRIDR*GRIDR*GRIDR)   // 1000
#define BMAX    2
#define NMAX    4096
#define PRADIUS 0.1f
#define QPB     8                     // queries per block == warps per block
#define CFEAT   64
#define FROW    (3 + CFEAT)           // 67
#define GPROW   (8 * FROW)            // 536 floats per query row

__device__ int    g_start [BMAX * (NCELL + 1)];
__device__ float4 g_sorted[BMAX * NMAX];   // x,y,z, w = bitcast(orig index)

__device__ __forceinline__ int cell_of(float x, float y, float z) {
    int cx = (int)(x * 10.0f); cx = min(max(cx, 0), GRIDR - 1);
    int cy = (int)(y * 10.0f); cy = min(max(cy, 0), GRIDR - 1);
    int cz = (int)(z * 10.0f); cz = min(max(cz, 0), GRIDR - 1);
    return (cx * GRIDR + cy) * GRIDR + cz;
}

// One block per batch. Histogram + warp-shuffle scan + scatter via smem.
__global__ __launch_bounds__(1024) void k_build(const float* __restrict__ xyz,
                                                int N) {
    __shared__ int s_cur [NCELL];
    __shared__ int s_wsum[32];

    int b   = blockIdx.x;
    int tid = threadIdx.x;
    int wid = tid >> 5;
    int lid = tid & 31;
    const float* xb = xyz + (size_t)b * N * 3;

    if (tid < NCELL) s_cur[tid] = 0;
    __syncthreads();

    const int PT = (NMAX + 1023) / 1024;   // 4
    float px[PT], py[PT], pz[PT];
    int   pc[PT];
    #pragma unroll
    for (int p = 0; p < PT; p++) {
        int i = tid + p * 1024;
        pc[p] = -1;
        if (i < N) {
            px[p] = xb[3 * i + 0];
            py[p] = xb[3 * i + 1];
            pz[p] = xb[3 * i + 2];
            pc[p] = cell_of(px[p], py[p], pz[p]);
            atomicAdd(&s_cur[pc[p]], 1);
        }
    }
    __syncthreads();

    int v = (tid < NCELL) ? s_cur[tid] : 0;
    int x = v;
    #pragma unroll
    for (int off = 1; off < 32; off <<= 1) {
        int y = __shfl_up_sync(0xFFFFFFFFu, x, off);
        if (lid >= off) x += y;
    }
    if (lid == 31) s_wsum[wid] = x;
    __syncthreads();
    if (wid == 0) {
        int y = s_wsum[lid];
        #pragma unroll
        for (int off = 1; off < 32; off <<= 1) {
            int z2 = __shfl_up_sync(0xFFFFFFFFu, y, off);
            if (lid >= off) y += z2;
        }
        s_wsum[lid] = y;
    }
    __syncthreads();
    int incl = x + (wid > 0 ? s_wsum[wid - 1] : 0);
    if (tid < NCELL) {
        int excl = incl - v;
        g_start[b * (NCELL + 1) + tid] = excl;
        s_cur[tid] = excl;
        if (tid == NCELL - 1)
            g_start[b * (NCELL + 1) + NCELL] = incl;
    }
    __syncthreads();

    float4* dst = g_sorted + (size_t)b * NMAX;
    #pragma unroll
    for (int p = 0; p < PT; p++) {
        if (pc[p] >= 0) {
            int pos = atomicAdd(&s_cur[pc[p]], 1);
            int i = tid + p * 1024;
            dst[pos] = make_float4(px[p], py[p], pz[p], __int_as_float(i));
        }
    }
}

// One warp per query; flattened-span candidate loop; no block barriers.
__global__ __launch_bounds__(QPB * 32)
void k_query_gather(const float* __restrict__ xyz,
                    const float* __restrict__ pts,
                    float* __restrict__ gxyz,
                    float* __restrict__ gp,
                    float* __restrict__ idx_f,
                    int B, int N) {
    __shared__ unsigned long long s_key [QPB][8];
    __shared__ int                s_excl[QPB][9];
    __shared__ int                s_dlt [QPB][9];
    __shared__ alignas(16) float  s_stage[QPB][GPROW];  // 8 x 536
    __shared__ alignas(16) float  s_gx   [QPB][24];

    const int tid  = threadIdx.x;
    const int w    = tid >> 5;
    const int lane = tid & 31;
    const int w0b  = blockIdx.x * QPB;     // first global query of block

    // block never straddles a batch (N % QPB == 0)
    const int b  = w0b / N;
    const int i0 = w0b - b * N;
    const int iq = i0 + w;                 // this warp's query
    const float* xb = xyz + (size_t)b * N * 3;

    // seed winner keys: (FLT_MAX, self)
    if (lane < 8)
        s_key[w][lane] =
            ((unsigned long long)0x7F7FFFFFull << 32) | (unsigned)iq;

    const float xi = xb[3 * iq + 0], yi = xb[3 * iq + 1], zi = xb[3 * iq + 2];

    int cx = min(max((int)(xi * 10.0f), 0), GRIDR - 1);
    int cy = min(max((int)(yi * 10.0f), 0), GRIDR - 1);
    int cz = min(max((int)(zi * 10.0f), 0), GRIDR - 1);
    int ax0 = max(cx - 1, 0), ax1 = min(cx + 1, GRIDR - 1);
    int ay0 = max(cy - 1, 0), ay1 = min(cy + 1, GRIDR - 1);
    int az0 = max(cz - 1, 0), az1 = min(cz + 1, GRIDR - 1);
    int ny = ay1 - ay0 + 1;
    int ns = (ax1 - ax0 + 1) * ny;         // 4..9 spans

    const int sbase = b * (NCELL + 1);
    const float4* __restrict__ srt = g_sorted + (size_t)b * NMAX;

    // parallel span-range fetch (lanes 0..ns-1), then flatten via prefix scan
    int rs = 0, re = 0;
    if (lane < ns) {
        int dxy = lane / ny;
        int rowc = ((ax0 + dxy) * GRIDR + (ay0 + lane - dxy * ny)) * GRIDR;
        rs = g_start[sbase + rowc + az0];
        re = g_start[sbase + rowc + az1 + 1];
    }
    int sz = re - rs;                      // 0 for lane >= ns
    int incl = sz;
    #pragma unroll
    for (int off = 1; off < 32; off <<= 1) {
        int t = __shfl_up_sync(0xFFFFFFFFu, incl, off);
        if (lane >= off) incl += t;
    }
    const int total = __shfl_sync(0xFFFFFFFFu, incl, ns - 1);
    if (lane < ns) {
        int ex = incl - sz;
        s_excl[w][lane] = ex;
        s_dlt [w][lane] = rs - ex;
    }
    __syncwarp();

    // flattened candidate loop: ~4 dense iterations, independent loads
    for (int c = lane; c < total; c += 32) {
        int dlt = s_dlt[w][0];
        #pragma unroll 8
        for (int s = 1; s < ns; ++s)
            if (c >= s_excl[w][s]) dlt = s_dlt[w][s];
        float4 p = srt[c + dlt];
        float dx = p.x - xi;
        float dy = p.y - yi;
        float dz = p.z - zi;
        if (fabsf(dx) < PRADIUS && fabsf(dy) < PRADIUS &&
            fabsf(dz) < PRADIUS) {
            unsigned j = (unsigned)__float_as_int(p.w);
            float d = __fadd_rn(
                __fadd_rn(__fmul_rn(dx, dx), __fmul_rn(dy, dy)),
                __fmul_rn(dz, dz));
            unsigned long long ck =
                ((unsigned long long)(unsigned)__float_as_int(d) << 32) | j;
            int oct = ((dx > 0.0f) ? 4 : 0) |
                      ((dy > 0.0f) ? 2 : 0) |
                      ((dz > 0.0f) ? 1 : 0);
            atomicMin(&s_key[w][oct], ck);
        }
    }
    __syncwarp();

    // publish idx (8 contiguous floats per query)
    if (lane < 8)
        idx_f[(size_t)(w0b + w) * 8 + lane] =
            (float)(int)(unsigned)(s_key[w][lane] & 0xFFFFFFFFull);

    // centered xyz: 24 values (lanes 0..23)
    if (lane < 24) {
        int o = lane / 3;
        int c = lane - o * 3;
        int jj = (int)(unsigned)(s_key[w][o] & 0xFFFFFFFFull);
        float v = xb[3 * jj + c] - xb[3 * iq + c];
        s_stage[w][o * FROW + c] = v;
        s_gx[w][lane] = v;
    }

    // features: 8 octants x 16 float4 = 128 vector loads, 4 dense iterations
    const float4* __restrict__ pb4 =
        (const float4*)(pts + (size_t)b * N * CFEAT);
    #pragma unroll
    for (int t0 = 0; t0 < 4; t0++) {
        int t  = lane + t0 * 32;     // 0..127
        int o  = t >> 4;
        int q  = t & 15;
        int jj = (int)(unsigned)(s_key[w][o] & 0xFFFFFFFFull);
        float4 f4 = pb4[(size_t)jj * 16 + q];
        int base = o * FROW + 3 + q * 4;
        s_stage[w][base + 0] = f4.x;
        s_stage[w][base + 1] = f4.y;
        s_stage[w][base + 2] = f4.z;
        s_stage[w][base + 3] = f4.w;
    }
    __syncwarp();

    // write-out: 536 floats = 134 aligned float4 per query row
    float4*       gpo = (float4*)(gp + (size_t)(w0b + w) * GPROW);
    const float4* st4 = (const float4*)s_stage[w];
    #pragma unroll
    for (int f = lane; f < GPROW / 4; f += 32)
        gpo[f] = st4[f];
    if (lane < 6)
        ((float4*)(gxyz + (size_t)(w0b + w) * 24))[lane] =
            ((const float4*)s_gx[w])[lane];
}

extern "C" void kernel_launch(void* const* d_in, const int* in_sizes, int n_in,
                              void* d_out, int out_size) {
    const float* xyz = (const float*)d_in[0];
    const float* pts = (const float*)d_in[1];
    float* out = (float*)d_out;

    int BN = in_sizes[0] / 3;       // B*N = 8192
    int B  = 2;
    int N  = BN / B;                // 4096

    size_t nG = (size_t)BN * 8;
    float* gxyz  = out;
    float* gp    = out + nG * 3;
    float* idx_f = out + nG * 3 + nG * (size_t)FROW;

    k_build<<<B, 1024>>>(xyz, N);
    k_query_gather<<<(BN + QPB - 1) / QPB, QPB * 32>>>(
        xyz, pts, gxyz, gp, idx_f, B, N);
}